// round 15
// baseline (speedup 1.0000x reference)
#include <cuda_runtime.h>
#include <cuda_bf16.h>
#include <cstdint>
#include <cstddef>

// Problem constants
#define NB    8
#define CT    1024
#define LL    1024
#define HEADS 16
#define BN_EPS 1e-5f

// ---------------------------------------------------------------------------
// Scratch (static device allocations). Referenced ONLY from device code.
// ---------------------------------------------------------------------------
__device__ __nv_bfloat16 g_kT[(size_t)NB * HEADS * LL * 32];  // 8 MB  [n][h][l][32d]
__device__ __nv_bfloat16 g_qT[(size_t)NB * HEADS * LL * 32];  // 8 MB  [n][h][l][32d]
__device__ __nv_bfloat16 g_vB[(size_t)NB * CT * LL];          // 16 MB [n][c][l] == per-head [d][k]
__device__ float         g_mid[(size_t)NB * CT * LL];         // 32 MB tokens + kqv

// ---------------------------------------------------------------------------
// mma.sync / ldmatrix / cp.async helpers (base PTX, sm_80+)
// ---------------------------------------------------------------------------
__device__ __forceinline__ uint32_t smem_u32(const void* p) {
    uint32_t a;
    asm("{ .reg .u64 t; cvta.to.shared.u64 t, %1; cvt.u32.u64 %0, t; }"
        : "=r"(a) : "l"(p));
    return a;
}

#define LDSM_X4(R, A)                                                        \
    asm volatile("ldmatrix.sync.aligned.m8n8.x4.shared.b16 {%0,%1,%2,%3}, [%4];" \
                 : "=r"((R)[0]), "=r"((R)[1]), "=r"((R)[2]), "=r"((R)[3])    \
                 : "r"(A))

#define MMA16816(C, A, B0, B1)                                               \
    asm volatile("mma.sync.aligned.m16n8k16.row.col.f32.bf16.bf16.f32 "      \
                 "{%0,%1,%2,%3}, {%4,%5,%6,%7}, {%8,%9}, {%0,%1,%2,%3};"     \
                 : "+f"((C)[0]), "+f"((C)[1]), "+f"((C)[2]), "+f"((C)[3])    \
                 : "r"((A)[0]), "r"((A)[1]), "r"((A)[2]), "r"((A)[3]),       \
                   "r"(B0), "r"(B1))

#define MMA_TF32(C, A, B0, B1)                                               \
    asm volatile("mma.sync.aligned.m16n8k8.row.col.f32.tf32.tf32.f32 "       \
                 "{%0,%1,%2,%3}, {%4,%5,%6,%7}, {%8,%9}, {%0,%1,%2,%3};"     \
                 : "+f"((C)[0]), "+f"((C)[1]), "+f"((C)[2]), "+f"((C)[3])    \
                 : "r"((A)[0]), "r"((A)[1]), "r"((A)[2]), "r"((A)[3]),       \
                   "r"(B0), "r"(B1))

#define CP_ASYNC16(smem, gptr)                                               \
    asm volatile("cp.async.cg.shared.global [%0], [%1], 16;"                 \
                 :: "r"(smem), "l"(gptr))
#define CP_COMMIT() asm volatile("cp.async.commit_group;" ::: "memory")
#define CP_WAIT(N)  asm volatile("cp.async.wait_group %0;" :: "n"(N) : "memory")

__device__ __forceinline__ uint32_t packbf2(float x, float y) {
    __nv_bfloat162 t = __floats2bfloat162_rn(x, y);
    return *(uint32_t*)&t;
}
__device__ __forceinline__ float ex2f(float x) {
    float r;
    asm("ex2.approx.ftz.f32 %0, %1;" : "=f"(r) : "f"(x));
    return r;
}

// Conv smem geometry (CO_TILE=64, L=128) — proven strides
#define CV_WS  36
#define CV_XS  136
#define CV_WSZ (64 * CV_WS)
#define CV_XSZ (32 * CV_XS)
#define CV_SMEM ((2 * CV_WSZ + 2 * CV_XSZ) * 4)   // 53248 B -> 4 blocks/SM

// conv output modes
#define OUT_KT  0
#define OUT_QT  1
#define OUT_VB  2

#define KQV_TILES 2048
#define KQV_GRID  592     // 148 SM x 4 resident blocks

// ---------------------------------------------------------------------------
// Merged K/Q/V conv + BN, PERSISTENT: 592 blocks loop over 2048 tiles.
// tf32 raw-bits mainloop (R12-proven), CO_TILE=64.
// Tile decode: n = t>>8, y = (t>>3)&31 (0..7 K, 8..15 Q, 16..31 V), x = t&7.
// ---------------------------------------------------------------------------
__global__ __launch_bounds__(256) void kqv_conv_kernel(
    const float* __restrict__ tokens,
    const float* __restrict__ kw, const float* __restrict__ kb,
    const float* __restrict__ kg, const float* __restrict__ kbe,
    const float* __restrict__ km, const float* __restrict__ kvv,
    const float* __restrict__ qw, const float* __restrict__ qb,
    const float* __restrict__ qg, const float* __restrict__ qbe,
    const float* __restrict__ qm, const float* __restrict__ qvv,
    const float* __restrict__ vw, const float* __restrict__ vb,
    const float* __restrict__ vg, const float* __restrict__ vbe,
    const float* __restrict__ vm, const float* __restrict__ vvv)
{
    extern __shared__ uint32_t sm_u[];
    uint32_t* Wsm = sm_u;
    uint32_t* Xsm = sm_u + 2 * CV_WSZ;
    const uint32_t ws_addr = smem_u32(Wsm);
    const uint32_t xs_addr = smem_u32(Xsm);

    const int tid  = threadIdx.x;
    const int wrp  = tid >> 5;
    const int lane = tid & 31;
    const int grp  = lane >> 2;
    const int tg   = lane & 3;
    const int wm   = wrp >> 2;     // 0..1
    const int wn   = wrp & 3;      // 0..3

    for (int tile = blockIdx.x; tile < KQV_TILES; tile += KQV_GRID) {
        const int n  = tile >> 8;
        const int y  = (tile >> 3) & 31;
        const int l0 = (tile & 7) * 128;

        const int mode = (y < 8) ? OUT_KT : (y < 16) ? OUT_QT : OUT_VB;
        const int ly   = (mode == OUT_KT) ? y : (mode == OUT_QT) ? (y - 8) : (y - 16);
        const int co0  = ly * 64;

        const float *w, *bias, *gamma, *beta, *mean, *var;
        int cout_per_g;
        if (mode == OUT_KT)      { w = kw; bias = kb; gamma = kg; beta = kbe; mean = km; var = kvv; cout_per_g = 64; }
        else if (mode == OUT_QT) { w = qw; bias = qb; gamma = qg; beta = qbe; mean = qm; var = qvv; cout_per_g = 64; }
        else                     { w = vw; bias = vb; gamma = vg; beta = vbe; mean = vm; var = vvv; cout_per_g = 128; }

        const int g = co0 / cout_per_g;
        const float* xg = tokens + ((size_t)n * CT + (size_t)g * 128) * LL + l0;

        float c[2][4][4];
#pragma unroll
        for (int mt = 0; mt < 2; mt++)
#pragma unroll
            for (int nt = 0; nt < 4; nt++)
#pragma unroll
                for (int j = 0; j < 4; j++) c[mt][nt][j] = 0.f;

        auto issue = [&](int ch, int buf) {
#pragma unroll
            for (int i = 0; i < 4; i++) {      // X: 32 x 128
                int idx = tid + i * 256;
                int r = idx >> 5, c4 = idx & 31;
                uint32_t dst = xs_addr + (uint32_t)(buf * CV_XSZ + r * CV_XS + c4 * 4) * 4;
                CP_ASYNC16(dst, xg + (size_t)(ch * 32 + r) * LL + c4 * 4);
            }
#pragma unroll
            for (int i = 0; i < 2; i++) {      // W: 64 x 32
                int idx = tid + i * 256;
                int r = idx >> 3, k4 = idx & 7;
                uint32_t dst = ws_addr + (uint32_t)(buf * CV_WSZ + r * CV_WS + k4 * 4) * 4;
                CP_ASYNC16(dst, w + (size_t)(co0 + r) * 128 + ch * 32 + k4 * 4);
            }
            CP_COMMIT();
        };

        issue(0, 0);
        for (int ch = 0; ch < 4; ch++) {       // cin 128
            if (ch + 1 < 4) { issue(ch + 1, (ch + 1) & 1); CP_WAIT(1); }
            else            { CP_WAIT(0); }
            __syncthreads();

            const uint32_t* Wb = Wsm + (ch & 1) * CV_WSZ;
            const uint32_t* Xb = Xsm + (ch & 1) * CV_XSZ;

#pragma unroll
            for (int ks = 0; ks < 4; ks++) {
                uint32_t a[2][4], b[4][2];
#pragma unroll
                for (int mt = 0; mt < 2; mt++) {
                    int r0 = (wm * 32 + mt * 16 + grp) * CV_WS + ks * 8 + tg;
                    a[mt][0] = Wb[r0];
                    a[mt][1] = Wb[r0 + 8 * CV_WS];
                    a[mt][2] = Wb[r0 + 4];
                    a[mt][3] = Wb[r0 + 8 * CV_WS + 4];
                }
#pragma unroll
                for (int nt = 0; nt < 4; nt++) {
                    int xb = (ks * 8 + tg) * CV_XS + wn * 32 + nt * 8 + grp;
                    b[nt][0] = Xb[xb];
                    b[nt][1] = Xb[xb + 4 * CV_XS];
                }
#pragma unroll
                for (int mt = 0; mt < 2; mt++)
#pragma unroll
                    for (int nt = 0; nt < 4; nt++)
                        MMA_TF32(c[mt][nt], a[mt], b[nt][0], b[nt][1]);
            }
            __syncthreads();
        }

        // Epilogue: BN + mode-specific store
#pragma unroll
        for (int mt = 0; mt < 2; mt++) {
            int coA = co0 + wm * 32 + mt * 16 + grp;
            int coB = coA + 8;
            float invA = gamma[coA] * rsqrtf(var[coA] + BN_EPS);
            float shA  = bias[coA] * invA + beta[coA] - mean[coA] * invA;
            float invB = gamma[coB] * rsqrtf(var[coB] + BN_EPS);
            float shB  = bias[coB] * invB + beta[coB] - mean[coB] * invB;

#pragma unroll
            for (int nt = 0; nt < 4; nt++) {
                int col = l0 + wn * 32 + nt * 8 + tg * 2;
                float vA0 = c[mt][nt][0] * invA + shA;
                float vA1 = c[mt][nt][1] * invA + shA;
                float vB0 = c[mt][nt][2] * invB + shB;
                float vB1 = c[mt][nt][3] * invB + shB;

                if (mode == OUT_VB) {   // V: bf16 [n][co][l]
                    size_t iA = ((size_t)n * CT + coA) * LL + col;
                    size_t iB = ((size_t)n * CT + coB) * LL + col;
                    *(uint32_t*)&g_vB[iA] = packbf2(vA0, vA1);
                    *(uint32_t*)&g_vB[iB] = packbf2(vB0, vB1);
                } else {                // K/Q: bf16 transposed [n][h][l][32]
                    __nv_bfloat16* dst = (mode == OUT_KT) ? g_kT : g_qT;
                    int hA = coA >> 5, dA = coA & 31;
                    int hB = coB >> 5, dB = coB & 31;
                    size_t bA = (((size_t)n * HEADS + hA) * LL + col) * 32 + dA;
                    size_t bB = (((size_t)n * HEADS + hB) * LL + col) * 32 + dB;
                    dst[bA]      = __float2bfloat16(vA0);
                    dst[bA + 32] = __float2bfloat16(vA1);
                    dst[bB]      = __float2bfloat16(vB0);
                    dst[bB + 32] = __float2bfloat16(vB1);
                }
            }
        }
        // last chunk ended with __syncthreads(); next tile's issue is safe
    }
}

// ---------------------------------------------------------------------------
// FF conv (groups=1) + BN + residual: tf32 raw-bits, CO_TILE=64, L=128
// (R12-proven config — measured best).
// ---------------------------------------------------------------------------
__global__ __launch_bounds__(256) void ff_conv_kernel(
    const float* __restrict__ w,
    const float* __restrict__ bias, const float* __restrict__ gamma,
    const float* __restrict__ beta, const float* __restrict__ mean,
    const float* __restrict__ var, float* __restrict__ out)
{
    extern __shared__ uint32_t sm_u[];
    uint32_t* Wsm = sm_u;
    uint32_t* Xsm = sm_u + 2 * CV_WSZ;
    const uint32_t ws_addr = smem_u32(Wsm);
    const uint32_t xs_addr = smem_u32(Xsm);

    const int n   = blockIdx.z;
    const int co0 = blockIdx.y * 64;
    const int l0  = blockIdx.x * 128;

    const float* xg = g_mid + (size_t)n * CT * LL + l0;

    const int tid  = threadIdx.x;
    const int wrp  = tid >> 5;
    const int lane = tid & 31;
    const int grp  = lane >> 2;
    const int tg   = lane & 3;
    const int wm   = wrp >> 2;     // 0..1
    const int wn   = wrp & 3;      // 0..3

    float c[2][4][4];
#pragma unroll
    for (int mt = 0; mt < 2; mt++)
#pragma unroll
        for (int nt = 0; nt < 4; nt++)
#pragma unroll
            for (int j = 0; j < 4; j++) c[mt][nt][j] = 0.f;

    auto issue = [&](int ch, int buf) {
#pragma unroll
        for (int i = 0; i < 4; i++) {
            int idx = tid + i * 256;
            int r = idx >> 5, c4 = idx & 31;
            uint32_t dst = xs_addr + (uint32_t)(buf * CV_XSZ + r * CV_XS + c4 * 4) * 4;
            CP_ASYNC16(dst, xg + (size_t)(ch * 32 + r) * LL + c4 * 4);
        }
#pragma unroll
        for (int i = 0; i < 2; i++) {
            int idx = tid + i * 256;
            int r = idx >> 3, k4 = idx & 7;
            uint32_t dst = ws_addr + (uint32_t)(buf * CV_WSZ + r * CV_WS + k4 * 4) * 4;
            CP_ASYNC16(dst, w + (size_t)(co0 + r) * 1024 + ch * 32 + k4 * 4);
        }
        CP_COMMIT();
    };

    issue(0, 0);
    for (int ch = 0; ch < 32; ch++) {      // cin 1024
        if (ch + 1 < 32) { issue(ch + 1, (ch + 1) & 1); CP_WAIT(1); }
        else             { CP_WAIT(0); }
        __syncthreads();

        const uint32_t* Wb = Wsm + (ch & 1) * CV_WSZ;
        const uint32_t* Xb = Xsm + (ch & 1) * CV_XSZ;

#pragma unroll
        for (int ks = 0; ks < 4; ks++) {
            uint32_t a[2][4], b[4][2];
#pragma unroll
            for (int mt = 0; mt < 2; mt++) {
                int r0 = (wm * 32 + mt * 16 + grp) * CV_WS + ks * 8 + tg;
                a[mt][0] = Wb[r0];
                a[mt][1] = Wb[r0 + 8 * CV_WS];
                a[mt][2] = Wb[r0 + 4];
                a[mt][3] = Wb[r0 + 8 * CV_WS + 4];
            }
#pragma unroll
            for (int nt = 0; nt < 4; nt++) {
                int xb = (ks * 8 + tg) * CV_XS + wn * 32 + nt * 8 + grp;
                b[nt][0] = Xb[xb];
                b[nt][1] = Xb[xb + 4 * CV_XS];
            }
#pragma unroll
            for (int mt = 0; mt < 2; mt++)
#pragma unroll
                for (int nt = 0; nt < 4; nt++)
                    MMA_TF32(c[mt][nt], a[mt], b[nt][0], b[nt][1]);
        }
        __syncthreads();
    }

    // Epilogue: BN + residual (g_mid) -> out
#pragma unroll
    for (int mt = 0; mt < 2; mt++) {
        int coA = co0 + wm * 32 + mt * 16 + grp;
        int coB = coA + 8;
        float invA = gamma[coA] * rsqrtf(var[coA] + BN_EPS);
        float shA  = bias[coA] * invA + beta[coA] - mean[coA] * invA;
        float invB = gamma[coB] * rsqrtf(var[coB] + BN_EPS);
        float shB  = bias[coB] * invB + beta[coB] - mean[coB] * invB;

#pragma unroll
        for (int nt = 0; nt < 4; nt++) {
            int col = l0 + wn * 32 + nt * 8 + tg * 2;
            size_t iA = ((size_t)n * CT + coA) * LL + col;
            size_t iB = ((size_t)n * CT + coB) * LL + col;
            float vA0 = c[mt][nt][0] * invA + shA + g_mid[iA];
            float vA1 = c[mt][nt][1] * invA + shA + g_mid[iA + 1];
            float vB0 = c[mt][nt][2] * invB + shB + g_mid[iB];
            float vB1 = c[mt][nt][3] * invB + shB + g_mid[iB + 1];
            *(float2*)&out[iA] = make_float2(vA0, vA1);
            *(float2*)&out[iB] = make_float2(vB0, vB1);
        }
    }
}

// ---------------------------------------------------------------------------
// Attention (unchanged — measured 96.6 us, at bf16 mma.sync roofline).
// 8 warps x 16 q-rows, cp.async double-buffered K/V, ex2.approx.
// ---------------------------------------------------------------------------
#define ASMQ    0
#define ASMK    10240
#define ASMK_SZ 10240
#define ASMV    (ASMK + 2 * ASMK_SZ)
#define ASMV_SZ 17408
#define SM_ATT_TOTAL (ASMV + 2 * ASMV_SZ)   // 65536 B

__global__ __launch_bounds__(256) void attn_mma_kernel(
    const float* __restrict__ tokens)
{
    extern __shared__ char att_sm[];
    const uint32_t sb = smem_u32(att_sm);

    const int tid  = threadIdx.x;
    const int w    = tid >> 5;
    const int lane = tid & 31;
    const int grp  = lane >> 2;
    const int tg   = lane & 3;
    const int q0   = blockIdx.x * 128;
    const int h    = blockIdx.y;
    const int n    = blockIdx.z;

    const int rowoff = (lane & 7) + ((lane >> 4) & 1) * 8;
    const int colsel = (lane >> 3) & 1;

    {
        int row = tid >> 1, half = tid & 1;
        const uint4* src = (const uint4*)(g_qT +
            (((size_t)n * HEADS + h) * LL + q0 + row) * 32 + half * 16);
        uint4* dst = (uint4*)(att_sm + ASMQ + row * 80 + half * 32);
        dst[0] = src[0];
        dst[1] = src[1];
    }

    auto issue = [&](int c, int buf) {
        {
            int row = tid >> 1, half = tid & 1;
            const char* kg = (const char*)(g_kT +
                (((size_t)n * HEADS + h) * LL + c * 128 + row) * 32 + half * 16);
            uint32_t kdst = sb + ASMK + buf * ASMK_SZ + row * 80 + half * 32;
            CP_ASYNC16(kdst, kg);
            CP_ASYNC16(kdst + 16, kg + 16);
        }
        {
            int row = tid >> 2, quar = tid & 3;
            const char* vg = (const char*)(g_vB +
                ((size_t)n * CT + h * 64 + row) * LL + c * 128 + quar * 32);
            uint32_t vdst = sb + ASMV + buf * ASMV_SZ + row * 272 + quar * 64;
#pragma unroll
            for (int u = 0; u < 4; u++)
                CP_ASYNC16(vdst + u * 16, vg + u * 16);
        }
        CP_COMMIT();
    };

    issue(0, 0);
    __syncthreads();

    uint32_t qa[2][4];
    {
        int r = lane & 15, cb = (lane >> 4) * 16;
#pragma unroll
        for (int ks = 0; ks < 2; ks++) {
            uint32_t addr = sb + ASMQ + (uint32_t)((w * 16 + r) * 80 + ks * 32 + cb);
            LDSM_X4(qa[ks], addr);
        }
    }

    const float SC2 = 1.4426950408889634f / 32.0f;
    float o[8][4];
#pragma unroll
    for (int i = 0; i < 8; i++)
#pragma unroll
        for (int j = 0; j < 4; j++) o[i][j] = 0.f;
    float rs0 = 0.f, rs1 = 0.f;

    for (int c = 0; c < 8; c++) {
        if (c + 1 < 8) { issue(c + 1, (c + 1) & 1); CP_WAIT(1); }
        else           { CP_WAIT(0); }
        __syncthreads();

        const uint32_t kb = sb + ASMK + (c & 1) * ASMK_SZ;
        const uint32_t vb = sb + ASMV + (c & 1) * ASMV_SZ;

        float s[16][4];
#pragma unroll
        for (int i = 0; i < 16; i++)
#pragma unroll
            for (int j = 0; j < 4; j++) s[i][j] = 0.f;

#pragma unroll
        for (int np = 0; np < 8; np++) {
#pragma unroll
            for (int ks = 0; ks < 2; ks++) {
                uint32_t b[4];
                LDSM_X4(b, kb + (uint32_t)((np * 16 + rowoff) * 80
                                           + ks * 32 + colsel * 16));
                MMA16816(s[2 * np],     qa[ks], b[0], b[1]);
                MMA16816(s[2 * np + 1], qa[ks], b[2], b[3]);
            }
        }

#pragma unroll
        for (int kk = 0; kk < 8; kk++) {
            float e0a = ex2f(s[2 * kk][0] * SC2);
            float e0b = ex2f(s[2 * kk][1] * SC2);
            float e0c = ex2f(s[2 * kk][2] * SC2);
            float e0d = ex2f(s[2 * kk][3] * SC2);
            float e1a = ex2f(s[2 * kk + 1][0] * SC2);
            float e1b = ex2f(s[2 * kk + 1][1] * SC2);
            float e1c = ex2f(s[2 * kk + 1][2] * SC2);
            float e1d = ex2f(s[2 * kk + 1][3] * SC2);
            rs0 += e0a + e0b + e1a + e1b;
            rs1 += e0c + e0d + e1c + e1d;
            uint32_t a[4];
            a[0] = packbf2(e0a, e0b);
            a[1] = packbf2(e0c, e0d);
            a[2] = packbf2(e1a, e1b);
            a[3] = packbf2(e1c, e1d);

#pragma unroll
            for (int dp = 0; dp < 4; dp++) {
                uint32_t bv[4];
                LDSM_X4(bv, vb + (uint32_t)((dp * 16 + rowoff) * 272
                                            + kk * 32 + colsel * 16));
                MMA16816(o[2 * dp],     a, bv[0], bv[1]);
                MMA16816(o[2 * dp + 1], a, bv[2], bv[3]);
            }
        }
        __syncthreads();
    }

    rs0 += __shfl_xor_sync(0xFFFFFFFF, rs0, 1);
    rs0 += __shfl_xor_sync(0xFFFFFFFF, rs0, 2);
    rs1 += __shfl_xor_sync(0xFFFFFFFF, rs1, 1);
    rs1 += __shfl_xor_sync(0xFFFFFFFF, rs1, 2);
    const float inv0 = 1.0f / rs0;
    const float inv1 = 1.0f / rs1;

    const int qg0 = q0 + w * 16 + grp;
#pragma unroll
    for (int dt = 0; dt < 8; dt++) {
        int d = dt * 8 + tg * 2;
        size_t i00 = ((size_t)n * CT + h * 64 + d) * LL + qg0;
        size_t i01 = i00 + LL;
        g_mid[i00]     = tokens[i00]     + o[dt][0] * inv0;
        g_mid[i01]     = tokens[i01]     + o[dt][1] * inv0;
        g_mid[i00 + 8] = tokens[i00 + 8] + o[dt][2] * inv1;
        g_mid[i01 + 8] = tokens[i01 + 8] + o[dt][3] * inv1;
    }
}

// ---------------------------------------------------------------------------
extern "C" void kernel_launch(void* const* d_in, const int* in_sizes, int n_in,
                              void* d_out, int out_size)
{
    (void)in_sizes; (void)n_in; (void)out_size;
    const float* tokens = (const float*)d_in[0];
    const float* kw = (const float*)d_in[1];
    const float* kb = (const float*)d_in[2];
    const float* kg = (const float*)d_in[3];
    const float* kbe = (const float*)d_in[4];
    const float* km = (const float*)d_in[5];
    const float* kvv = (const float*)d_in[6];
    const float* qw = (const float*)d_in[7];
    const float* qb = (const float*)d_in[8];
    const float* qg = (const float*)d_in[9];
    const float* qbe = (const float*)d_in[10];
    const float* qm = (const float*)d_in[11];
    const float* qvv = (const float*)d_in[12];
    const float* vw = (const float*)d_in[13];
    const float* vb = (const float*)d_in[14];
    const float* vg = (const float*)d_in[15];
    const float* vbe = (const float*)d_in[16];
    const float* vm = (const float*)d_in[17];
    const float* vvv = (const float*)d_in[18];
    const float* fw = (const float*)d_in[19];
    const float* fb = (const float*)d_in[20];
    const float* fg = (const float*)d_in[21];
    const float* fbe = (const float*)d_in[22];
    const float* fm = (const float*)d_in[23];
    const float* fvv = (const float*)d_in[24];

    cudaFuncSetAttribute(kqv_conv_kernel,
                         cudaFuncAttributeMaxDynamicSharedMemorySize, CV_SMEM);
    cudaFuncSetAttribute(ff_conv_kernel,
                         cudaFuncAttributeMaxDynamicSharedMemorySize, CV_SMEM);
    cudaFuncSetAttribute(attn_mma_kernel,
                         cudaFuncAttributeMaxDynamicSharedMemorySize, SM_ATT_TOTAL);

    // Merged K/Q/V convs (tf32), persistent: 592 blocks over 2048 tiles
    kqv_conv_kernel<<<KQV_GRID, 256, CV_SMEM>>>(
        tokens,
        kw, kb, kg, kbe, km, kvv,
        qw, qb, qg, qbe, qm, qvv,
        vw, vb, vg, vbe, vm, vvv);

    // Attention + residual -> g_mid
    attn_mma_kernel<<<dim3(8, HEADS, 8), 256, SM_ATT_TOTAL>>>(tokens);

    // FF conv (tf32, CO_TILE=64) + residual: g_mid -> d_out
    ff_conv_kernel<<<dim3(8, 16, 8), 256, CV_SMEM>>>(
        fw, fb, fg, fbe, fm, fvv, (float*)d_out);
}

// round 16
// speedup vs baseline: 1.0922x; 1.0922x over previous
#include <cuda_runtime.h>
#include <cuda_bf16.h>
#include <cuda_fp16.h>
#include <cstdint>
#include <cstddef>

// Problem constants
#define NB    8
#define CT    1024
#define LL    1024
#define HEADS 16
#define BN_EPS 1e-5f

// ---------------------------------------------------------------------------
// Scratch (static device allocations). Referenced ONLY from device code.
// ---------------------------------------------------------------------------
__device__ __nv_bfloat16 g_kT[(size_t)NB * HEADS * LL * 32];  // 8 MB  [n][h][l][32d]
__device__ __nv_bfloat16 g_qT[(size_t)NB * HEADS * LL * 32];  // 8 MB
__device__ __nv_bfloat16 g_vB[(size_t)NB * CT * LL];          // 16 MB [n][c][l]
__device__ float         g_mid[(size_t)NB * CT * LL];         // 32 MB tokens + kqv
__device__ __half        g_tokT[(size_t)NB * LL * CT];        // 16 MB [n][l][c] fp16
__device__ __half        g_midT[(size_t)NB * LL * CT];        // 16 MB [n][l][c] fp16
__device__ __half        g_kwh[512 * 128];
__device__ __half        g_qwh[512 * 128];
__device__ __half        g_vwh[1024 * 128];
__device__ __half        g_fwh[1024 * 1024];

// ---------------------------------------------------------------------------
// mma.sync / ldmatrix / cp.async helpers (base PTX, sm_80+)
// ---------------------------------------------------------------------------
__device__ __forceinline__ uint32_t smem_u32(const void* p) {
    uint32_t a;
    asm("{ .reg .u64 t; cvta.to.shared.u64 t, %1; cvt.u32.u64 %0, t; }"
        : "=r"(a) : "l"(p));
    return a;
}

#define LDSM_X4(R, A)                                                        \
    asm volatile("ldmatrix.sync.aligned.m8n8.x4.shared.b16 {%0,%1,%2,%3}, [%4];" \
                 : "=r"((R)[0]), "=r"((R)[1]), "=r"((R)[2]), "=r"((R)[3])    \
                 : "r"(A))

#define MMA16816(C, A, B0, B1)                                               \
    asm volatile("mma.sync.aligned.m16n8k16.row.col.f32.bf16.bf16.f32 "      \
                 "{%0,%1,%2,%3}, {%4,%5,%6,%7}, {%8,%9}, {%0,%1,%2,%3};"     \
                 : "+f"((C)[0]), "+f"((C)[1]), "+f"((C)[2]), "+f"((C)[3])    \
                 : "r"((A)[0]), "r"((A)[1]), "r"((A)[2]), "r"((A)[3]),       \
                   "r"(B0), "r"(B1))

#define MMA16816H(C, A, B0, B1)                                              \
    asm volatile("mma.sync.aligned.m16n8k16.row.col.f32.f16.f16.f32 "        \
                 "{%0,%1,%2,%3}, {%4,%5,%6,%7}, {%8,%9}, {%0,%1,%2,%3};"     \
                 : "+f"((C)[0]), "+f"((C)[1]), "+f"((C)[2]), "+f"((C)[3])    \
                 : "r"((A)[0]), "r"((A)[1]), "r"((A)[2]), "r"((A)[3]),       \
                   "r"(B0), "r"(B1))

#define CP_ASYNC16(smem, gptr)                                               \
    asm volatile("cp.async.cg.shared.global [%0], [%1], 16;"                 \
                 :: "r"(smem), "l"(gptr))
#define CP_COMMIT() asm volatile("cp.async.commit_group;" ::: "memory")
#define CP_WAIT(N)  asm volatile("cp.async.wait_group %0;" :: "n"(N) : "memory")

__device__ __forceinline__ uint32_t packbf2(float x, float y) {
    __nv_bfloat162 t = __floats2bfloat162_rn(x, y);
    return *(uint32_t*)&t;
}
__device__ __forceinline__ float ex2f(float x) {
    float r;
    asm("ex2.approx.ftz.f32 %0, %1;" : "=f"(r) : "f"(x));
    return r;
}

// conv output modes
#define OUT_KT  0
#define OUT_QT  1
#define OUT_VB  2

// fp16 conv tile geometry: W tile [64 co][32 k], X tile [128 l][32 k],
// rows padded to 40 halves (80 B) — the attn-proven conflict-free stride.
#define HW_STRIDE 40
#define HWT_SZ (64 * HW_STRIDE)    // halves per W stage
#define HXT_SZ (128 * HW_STRIDE)   // halves per X stage

// ---------------------------------------------------------------------------
// Weight conversion: kw/qw/vw/fw fp32 -> fp16. 1,310,720 elems total.
// ---------------------------------------------------------------------------
__global__ __launch_bounds__(256) void cvt_weights_kernel(
    const float* __restrict__ kw, const float* __restrict__ qw,
    const float* __restrict__ vw, const float* __restrict__ fw)
{
    int idx = (blockIdx.x * 256 + threadIdx.x) * 4;
    const float* s;
    __half* d;
    int off;
    if (idx < 65536)        { s = kw; d = g_kwh; off = idx; }
    else if (idx < 131072)  { s = qw; d = g_qwh; off = idx - 65536; }
    else if (idx < 262144)  { s = vw; d = g_vwh; off = idx - 131072; }
    else                    { s = fw; d = g_fwh; off = idx - 262144; }
    float4 v = *(const float4*)(s + off);
    __half2 h0 = __floats2half2_rn(v.x, v.y);
    __half2 h1 = __floats2half2_rn(v.z, v.w);
    uint2 u = {*(uint32_t*)&h0, *(uint32_t*)&h1};
    *(uint2*)(d + off) = u;
}

// ---------------------------------------------------------------------------
// Transpose-convert: fp32 [n][1024 c][1024 l] -> fp16 [n][1024 l][1024 c].
// 64x64 tiles via smem. src_is_mid/dst_is_mid select device symbols.
// ---------------------------------------------------------------------------
__global__ __launch_bounds__(256) void transpose_h_kernel(
    const float* __restrict__ src_ext, int src_is_mid, int dst_is_mid)
{
    __shared__ __half ts[64][72];
    const float* src = src_is_mid ? g_mid : src_ext;
    __half* dst = dst_is_mid ? g_midT : g_tokT;

    const int n  = blockIdx.z;
    const int c0 = blockIdx.y * 64;
    const int l0 = blockIdx.x * 64;
    const int tid = threadIdx.x;
    const int r = tid >> 2, q = tid & 3;

    const float* s = src + ((size_t)n * CT + c0 + r) * LL + l0 + q * 16;
#pragma unroll
    for (int j = 0; j < 4; j++) {
        float4 v = *(const float4*)(s + j * 4);
        ts[q * 16 + j * 4 + 0][r] = __float2half(v.x);
        ts[q * 16 + j * 4 + 1][r] = __float2half(v.y);
        ts[q * 16 + j * 4 + 2][r] = __float2half(v.z);
        ts[q * 16 + j * 4 + 3][r] = __float2half(v.w);
    }
    __syncthreads();

    __half* d = dst + ((size_t)n * LL + l0 + r) * CT + c0 + q * 16;
    uint4 u0 = *(uint4*)&ts[r][q * 16];
    uint4 u1 = *(uint4*)&ts[r][q * 16 + 8];
    *(uint4*)d = u0;
    *(uint4*)(d + 8) = u1;
}

// ---------------------------------------------------------------------------
// Merged K/Q/V conv + BN — fp16 mma.sync (2x tf32 rate).
// Grid y: 0..7 K, 8..15 Q, 16..31 V. Block 64co x 128l, 256 thr (2x4 warps).
// A = W[co][k] fp16 (ldmatrix, attn-Q pattern), B = Xt[l][k] fp16
// (ldmatrix, attn-K pattern). cp.async double-buffered, 4 chunks of k=32.
// ---------------------------------------------------------------------------
__global__ __launch_bounds__(256) void kqv_conv_kernel(
    const float* __restrict__ kb_, const float* __restrict__ kg_,
    const float* __restrict__ kbe, const float* __restrict__ km_,
    const float* __restrict__ kvv,
    const float* __restrict__ qb_, const float* __restrict__ qg_,
    const float* __restrict__ qbe, const float* __restrict__ qm_,
    const float* __restrict__ qvv,
    const float* __restrict__ vb_, const float* __restrict__ vg_,
    const float* __restrict__ vbe, const float* __restrict__ vm_,
    const float* __restrict__ vvv)
{
    __shared__ __half Wt[2 * HWT_SZ];
    __shared__ __half Xt[2 * HXT_SZ];
    const uint32_t wt_b = smem_u32(Wt);
    const uint32_t xt_b = smem_u32(Xt);

    const int n  = blockIdx.z;
    const int y  = blockIdx.y;
    const int l0 = blockIdx.x * 128;

    const int mode = (y < 8) ? OUT_KT : (y < 16) ? OUT_QT : OUT_VB;
    const int ly   = (mode == OUT_KT) ? y : (mode == OUT_QT) ? (y - 8) : (y - 16);
    const int co0  = ly * 64;

    const __half* wh;
    const float *bias, *gamma, *beta, *mean, *var;
    int cout_per_g;
    if (mode == OUT_KT)      { wh = g_kwh; bias = kb_; gamma = kg_; beta = kbe; mean = km_; var = kvv; cout_per_g = 64; }
    else if (mode == OUT_QT) { wh = g_qwh; bias = qb_; gamma = qg_; beta = qbe; mean = qm_; var = qvv; cout_per_g = 64; }
    else                     { wh = g_vwh; bias = vb_; gamma = vg_; beta = vbe; mean = vm_; var = vvv; cout_per_g = 128; }

    const int g    = co0 / cout_per_g;
    const int goff = g * 128;

    const int tid  = threadIdx.x;
    const int wrp  = tid >> 5;
    const int lane = tid & 31;
    const int grp  = lane >> 2;
    const int tg   = lane & 3;
    const int wm   = wrp >> 2;     // 0..1 -> 32 co rows
    const int wn   = wrp & 3;      // 0..3 -> 32 l cols

    const int rowoff = (lane & 7) + ((lane >> 4) & 1) * 8;
    const int colsel = (lane >> 3) & 1;

    float c[2][4][4];
#pragma unroll
    for (int mt = 0; mt < 2; mt++)
#pragma unroll
        for (int nt = 0; nt < 4; nt++)
#pragma unroll
            for (int j = 0; j < 4; j++) c[mt][nt][j] = 0.f;

    auto issue = [&](int ch, int buf) {
        {   // W: 64 rows x 64 B, 4 thr/row
            int r = tid >> 2, q = tid & 3;
            uint32_t dst = wt_b + (uint32_t)(buf * HWT_SZ + r * HW_STRIDE) * 2 + q * 16;
            CP_ASYNC16(dst, wh + (size_t)(co0 + r) * 128 + ch * 32 + q * 8);
        }
        {   // X: 128 rows x 64 B, 2 thr/row
            int r = tid >> 1, half = tid & 1;
            uint32_t dst = xt_b + (uint32_t)(buf * HXT_SZ + r * HW_STRIDE) * 2 + half * 32;
            const __half* sp = g_tokT + ((size_t)n * LL + l0 + r) * CT + goff + ch * 32 + half * 16;
            CP_ASYNC16(dst, sp);
            CP_ASYNC16(dst + 16, sp + 8);
        }
        CP_COMMIT();
    };

    issue(0, 0);
    for (int ch = 0; ch < 4; ch++) {
        if (ch + 1 < 4) { issue(ch + 1, (ch + 1) & 1); CP_WAIT(1); }
        else            { CP_WAIT(0); }
        __syncthreads();

        const uint32_t wb = wt_b + (uint32_t)((ch & 1) * HWT_SZ) * 2;
        const uint32_t xb = xt_b + (uint32_t)((ch & 1) * HXT_SZ) * 2;
        const int r  = lane & 15;
        const int cb = (lane >> 4) * 16;

#pragma unroll
        for (int ks = 0; ks < 2; ks++) {
            uint32_t a[2][4];
#pragma unroll
            for (int mt = 0; mt < 2; mt++)
                LDSM_X4(a[mt], wb + (uint32_t)((wm * 32 + mt * 16 + r) * 80
                                               + ks * 32 + cb));
#pragma unroll
            for (int np = 0; np < 2; np++) {
                uint32_t b[4];
                LDSM_X4(b, xb + (uint32_t)((wn * 32 + np * 16 + rowoff) * 80
                                           + ks * 32 + colsel * 16));
                MMA16816H(c[0][2 * np],     a[0], b[0], b[1]);
                MMA16816H(c[0][2 * np + 1], a[0], b[2], b[3]);
                MMA16816H(c[1][2 * np],     a[1], b[0], b[1]);
                MMA16816H(c[1][2 * np + 1], a[1], b[2], b[3]);
            }
        }
        __syncthreads();
    }

    // Epilogue: BN + mode-specific store (unchanged mapping)
#pragma unroll
    for (int mt = 0; mt < 2; mt++) {
        int coA = co0 + wm * 32 + mt * 16 + grp;
        int coB = coA + 8;
        float invA = gamma[coA] * rsqrtf(var[coA] + BN_EPS);
        float shA  = bias[coA] * invA + beta[coA] - mean[coA] * invA;
        float invB = gamma[coB] * rsqrtf(var[coB] + BN_EPS);
        float shB  = bias[coB] * invB + beta[coB] - mean[coB] * invB;

#pragma unroll
        for (int nt = 0; nt < 4; nt++) {
            int col = l0 + wn * 32 + nt * 8 + tg * 2;
            float vA0 = c[mt][nt][0] * invA + shA;
            float vA1 = c[mt][nt][1] * invA + shA;
            float vB0 = c[mt][nt][2] * invB + shB;
            float vB1 = c[mt][nt][3] * invB + shB;

            if (mode == OUT_VB) {
                size_t iA = ((size_t)n * CT + coA) * LL + col;
                size_t iB = ((size_t)n * CT + coB) * LL + col;
                *(uint32_t*)&g_vB[iA] = packbf2(vA0, vA1);
                *(uint32_t*)&g_vB[iB] = packbf2(vB0, vB1);
            } else {
                __nv_bfloat16* dst = (mode == OUT_KT) ? g_kT : g_qT;
                int hA = coA >> 5, dA = coA & 31;
                int hB = coB >> 5, dB = coB & 31;
                size_t bA = (((size_t)n * HEADS + hA) * LL + col) * 32 + dA;
                size_t bB = (((size_t)n * HEADS + hB) * LL + col) * 32 + dB;
                dst[bA]      = __float2bfloat16(vA0);
                dst[bA + 32] = __float2bfloat16(vA1);
                dst[bB]      = __float2bfloat16(vB0);
                dst[bB + 32] = __float2bfloat16(vB1);
            }
        }
    }
}

// ---------------------------------------------------------------------------
// FF conv (groups=1) + BN + residual — fp16 mma.sync.
// X from g_midT [n][l][c] fp16, W from g_fwh, residual from g_mid fp32.
// 32 chunks of k=32. Block 64co x 128l.
// ---------------------------------------------------------------------------
__global__ __launch_bounds__(256) void ff_conv_kernel(
    const float* __restrict__ bias, const float* __restrict__ gamma,
    const float* __restrict__ beta, const float* __restrict__ mean,
    const float* __restrict__ var, float* __restrict__ out)
{
    __shared__ __half Wt[2 * HWT_SZ];
    __shared__ __half Xt[2 * HXT_SZ];
    const uint32_t wt_b = smem_u32(Wt);
    const uint32_t xt_b = smem_u32(Xt);

    const int n   = blockIdx.z;
    const int co0 = blockIdx.y * 64;
    const int l0  = blockIdx.x * 128;

    const int tid  = threadIdx.x;
    const int wrp  = tid >> 5;
    const int lane = tid & 31;
    const int grp  = lane >> 2;
    const int tg   = lane & 3;
    const int wm   = wrp >> 2;
    const int wn   = wrp & 3;

    const int rowoff = (lane & 7) + ((lane >> 4) & 1) * 8;
    const int colsel = (lane >> 3) & 1;

    float c[2][4][4];
#pragma unroll
    for (int mt = 0; mt < 2; mt++)
#pragma unroll
        for (int nt = 0; nt < 4; nt++)
#pragma unroll
            for (int j = 0; j < 4; j++) c[mt][nt][j] = 0.f;

    auto issue = [&](int ch, int buf) {
        {
            int r = tid >> 2, q = tid & 3;
            uint32_t dst = wt_b + (uint32_t)(buf * HWT_SZ + r * HW_STRIDE) * 2 + q * 16;
            CP_ASYNC16(dst, g_fwh + (size_t)(co0 + r) * 1024 + ch * 32 + q * 8);
        }
        {
            int r = tid >> 1, half = tid & 1;
            uint32_t dst = xt_b + (uint32_t)(buf * HXT_SZ + r * HW_STRIDE) * 2 + half * 32;
            const __half* sp = g_midT + ((size_t)n * LL + l0 + r) * CT + ch * 32 + half * 16;
            CP_ASYNC16(dst, sp);
            CP_ASYNC16(dst + 16, sp + 8);
        }
        CP_COMMIT();
    };

    issue(0, 0);
    for (int ch = 0; ch < 32; ch++) {
        if (ch + 1 < 32) { issue(ch + 1, (ch + 1) & 1); CP_WAIT(1); }
        else             { CP_WAIT(0); }
        __syncthreads();

        const uint32_t wb = wt_b + (uint32_t)((ch & 1) * HWT_SZ) * 2;
        const uint32_t xb = xt_b + (uint32_t)((ch & 1) * HXT_SZ) * 2;
        const int r  = lane & 15;
        const int cb = (lane >> 4) * 16;

#pragma unroll
        for (int ks = 0; ks < 2; ks++) {
            uint32_t a[2][4];
#pragma unroll
            for (int mt = 0; mt < 2; mt++)
                LDSM_X4(a[mt], wb + (uint32_t)((wm * 32 + mt * 16 + r) * 80
                                               + ks * 32 + cb));
#pragma unroll
            for (int np = 0; np < 2; np++) {
                uint32_t b[4];
                LDSM_X4(b, xb + (uint32_t)((wn * 32 + np * 16 + rowoff) * 80
                                           + ks * 32 + colsel * 16));
                MMA16816H(c[0][2 * np],     a[0], b[0], b[1]);
                MMA16816H(c[0][2 * np + 1], a[0], b[2], b[3]);
                MMA16816H(c[1][2 * np],     a[1], b[0], b[1]);
                MMA16816H(c[1][2 * np + 1], a[1], b[2], b[3]);
            }
        }
        __syncthreads();
    }

    // Epilogue: BN + residual (g_mid fp32) -> out
#pragma unroll
    for (int mt = 0; mt < 2; mt++) {
        int coA = co0 + wm * 32 + mt * 16 + grp;
        int coB = coA + 8;
        float invA = gamma[coA] * rsqrtf(var[coA] + BN_EPS);
        float shA  = bias[coA] * invA + beta[coA] - mean[coA] * invA;
        float invB = gamma[coB] * rsqrtf(var[coB] + BN_EPS);
        float shB  = bias[coB] * invB + beta[coB] - mean[coB] * invB;

#pragma unroll
        for (int nt = 0; nt < 4; nt++) {
            int col = l0 + wn * 32 + nt * 8 + tg * 2;
            size_t iA = ((size_t)n * CT + coA) * LL + col;
            size_t iB = ((size_t)n * CT + coB) * LL + col;
            float vA0 = c[mt][nt][0] * invA + shA + g_mid[iA];
            float vA1 = c[mt][nt][1] * invA + shA + g_mid[iA + 1];
            float vB0 = c[mt][nt][2] * invB + shB + g_mid[iB];
            float vB1 = c[mt][nt][3] * invB + shB + g_mid[iB + 1];
            *(float2*)&out[iA] = make_float2(vA0, vA1);
            *(float2*)&out[iB] = make_float2(vB0, vB1);
        }
    }
}

// ---------------------------------------------------------------------------
// Attention (unchanged — measured 96.6 us, at bf16 mma.sync roofline).
// ---------------------------------------------------------------------------
#define ASMQ    0
#define ASMK    10240
#define ASMK_SZ 10240
#define ASMV    (ASMK + 2 * ASMK_SZ)
#define ASMV_SZ 17408
#define SM_ATT_TOTAL (ASMV + 2 * ASMV_SZ)   // 65536 B

__global__ __launch_bounds__(256) void attn_mma_kernel(
    const float* __restrict__ tokens)
{
    extern __shared__ char att_sm[];
    const uint32_t sb = smem_u32(att_sm);

    const int tid  = threadIdx.x;
    const int w    = tid >> 5;
    const int lane = tid & 31;
    const int grp  = lane >> 2;
    const int tg   = lane & 3;
    const int q0   = blockIdx.x * 128;
    const int h    = blockIdx.y;
    const int n    = blockIdx.z;

    const int rowoff = (lane & 7) + ((lane >> 4) & 1) * 8;
    const int colsel = (lane >> 3) & 1;

    {
        int row = tid >> 1, half = tid & 1;
        const uint4* src = (const uint4*)(g_qT +
            (((size_t)n * HEADS + h) * LL + q0 + row) * 32 + half * 16);
        uint4* dst = (uint4*)(att_sm + ASMQ + row * 80 + half * 32);
        dst[0] = src[0];
        dst[1] = src[1];
    }

    auto issue = [&](int c, int buf) {
        {
            int row = tid >> 1, half = tid & 1;
            const char* kg = (const char*)(g_kT +
                (((size_t)n * HEADS + h) * LL + c * 128 + row) * 32 + half * 16);
            uint32_t kdst = sb + ASMK + buf * ASMK_SZ + row * 80 + half * 32;
            CP_ASYNC16(kdst, kg);
            CP_ASYNC16(kdst + 16, kg + 16);
        }
        {
            int row = tid >> 2, quar = tid & 3;
            const char* vg = (const char*)(g_vB +
                ((size_t)n * CT + h * 64 + row) * LL + c * 128 + quar * 32);
            uint32_t vdst = sb + ASMV + buf * ASMV_SZ + row * 272 + quar * 64;
#pragma unroll
            for (int u = 0; u < 4; u++)
                CP_ASYNC16(vdst + u * 16, vg + u * 16);
        }
        CP_COMMIT();
    };

    issue(0, 0);
    __syncthreads();

    uint32_t qa[2][4];
    {
        int r = lane & 15, cb = (lane >> 4) * 16;
#pragma unroll
        for (int ks = 0; ks < 2; ks++) {
            uint32_t addr = sb + ASMQ + (uint32_t)((w * 16 + r) * 80 + ks * 32 + cb);
            LDSM_X4(qa[ks], addr);
        }
    }

    const float SC2 = 1.4426950408889634f / 32.0f;
    float o[8][4];
#pragma unroll
    for (int i = 0; i < 8; i++)
#pragma unroll
        for (int j = 0; j < 4; j++) o[i][j] = 0.f;
    float rs0 = 0.f, rs1 = 0.f;

    for (int c = 0; c < 8; c++) {
        if (c + 1 < 8) { issue(c + 1, (c + 1) & 1); CP_WAIT(1); }
        else           { CP_WAIT(0); }
        __syncthreads();

        const uint32_t kb = sb + ASMK + (c & 1) * ASMK_SZ;
        const uint32_t vb = sb + ASMV + (c & 1) * ASMV_SZ;

        float s[16][4];
#pragma unroll
        for (int i = 0; i < 16; i++)
#pragma unroll
            for (int j = 0; j < 4; j++) s[i][j] = 0.f;

#pragma unroll
        for (int np = 0; np < 8; np++) {
#pragma unroll
            for (int ks = 0; ks < 2; ks++) {
                uint32_t b[4];
                LDSM_X4(b, kb + (uint32_t)((np * 16 + rowoff) * 80
                                           + ks * 32 + colsel * 16));
                MMA16816(s[2 * np],     qa[ks], b[0], b[1]);
                MMA16816(s[2 * np + 1], qa[ks], b[2], b[3]);
            }
        }

#pragma unroll
        for (int kk = 0; kk < 8; kk++) {
            float e0a = ex2f(s[2 * kk][0] * SC2);
            float e0b = ex2f(s[2 * kk][1] * SC2);
            float e0c = ex2f(s[2 * kk][2] * SC2);
            float e0d = ex2f(s[2 * kk][3] * SC2);
            float e1a = ex2f(s[2 * kk + 1][0] * SC2);
            float e1b = ex2f(s[2 * kk + 1][1] * SC2);
            float e1c = ex2f(s[2 * kk + 1][2] * SC2);
            float e1d = ex2f(s[2 * kk + 1][3] * SC2);
            rs0 += e0a + e0b + e1a + e1b;
            rs1 += e0c + e0d + e1c + e1d;
            uint32_t a[4];
            a[0] = packbf2(e0a, e0b);
            a[1] = packbf2(e0c, e0d);
            a[2] = packbf2(e1a, e1b);
            a[3] = packbf2(e1c, e1d);

#pragma unroll
            for (int dp = 0; dp < 4; dp++) {
                uint32_t bv[4];
                LDSM_X4(bv, vb + (uint32_t)((dp * 16 + rowoff) * 272
                                            + kk * 32 + colsel * 16));
                MMA16816(o[2 * dp],     a, bv[0], bv[1]);
                MMA16816(o[2 * dp + 1], a, bv[2], bv[3]);
            }
        }
        __syncthreads();
    }

    rs0 += __shfl_xor_sync(0xFFFFFFFF, rs0, 1);
    rs0 += __shfl_xor_sync(0xFFFFFFFF, rs0, 2);
    rs1 += __shfl_xor_sync(0xFFFFFFFF, rs1, 1);
    rs1 += __shfl_xor_sync(0xFFFFFFFF, rs1, 2);
    const float inv0 = 1.0f / rs0;
    const float inv1 = 1.0f / rs1;

    const int qg0 = q0 + w * 16 + grp;
#pragma unroll
    for (int dt = 0; dt < 8; dt++) {
        int d = dt * 8 + tg * 2;
        size_t i00 = ((size_t)n * CT + h * 64 + d) * LL + qg0;
        size_t i01 = i00 + LL;
        g_mid[i00]     = tokens[i00]     + o[dt][0] * inv0;
        g_mid[i01]     = tokens[i01]     + o[dt][1] * inv0;
        g_mid[i00 + 8] = tokens[i00 + 8] + o[dt][2] * inv1;
        g_mid[i01 + 8] = tokens[i01 + 8] + o[dt][3] * inv1;
    }
}

// ---------------------------------------------------------------------------
extern "C" void kernel_launch(void* const* d_in, const int* in_sizes, int n_in,
                              void* d_out, int out_size)
{
    (void)in_sizes; (void)n_in; (void)out_size;
    const float* tokens = (const float*)d_in[0];
    const float* kw = (const float*)d_in[1];
    const float* kb = (const float*)d_in[2];
    const float* kg = (const float*)d_in[3];
    const float* kbe = (const float*)d_in[4];
    const float* km = (const float*)d_in[5];
    const float* kvv = (const float*)d_in[6];
    const float* qw = (const float*)d_in[7];
    const float* qb = (const float*)d_in[8];
    const float* qg = (const float*)d_in[9];
    const float* qbe = (const float*)d_in[10];
    const float* qm = (const float*)d_in[11];
    const float* qvv = (const float*)d_in[12];
    const float* vw = (const float*)d_in[13];
    const float* vb = (const float*)d_in[14];
    const float* vg = (const float*)d_in[15];
    const float* vbe = (const float*)d_in[16];
    const float* vm = (const float*)d_in[17];
    const float* vvv = (const float*)d_in[18];
    const float* fw = (const float*)d_in[19];
    const float* fb = (const float*)d_in[20];
    const float* fg = (const float*)d_in[21];
    const float* fbe = (const float*)d_in[22];
    const float* fm = (const float*)d_in[23];
    const float* fvv = (const float*)d_in[24];

    cudaFuncSetAttribute(attn_mma_kernel,
                         cudaFuncAttributeMaxDynamicSharedMemorySize, SM_ATT_TOTAL);

    // 1. Convert all conv weights to fp16
    cvt_weights_kernel<<<1280, 256>>>(kw, qw, vw, fw);
    // 2. Transpose-convert tokens -> g_tokT fp16 [n][l][c]
    transpose_h_kernel<<<dim3(16, 16, 8), 256>>>(tokens, 0, 0);
    // 3. Merged K/Q/V convs (fp16 mma)
    kqv_conv_kernel<<<dim3(8, 32, 8), 256>>>(
        kb, kg, kbe, km, kvv,
        qb, qg, qbe, qm, qvv,
        vb, vg, vbe, vm, vvv);
    // 4. Attention + residual -> g_mid fp32
    attn_mma_kernel<<<dim3(8, HEADS, 8), 256, SM_ATT_TOTAL>>>(tokens);
    // 5. Transpose-convert g_mid -> g_midT fp16 [n][l][c]
    transpose_h_kernel<<<dim3(16, 16, 8), 256>>>(nullptr, 1, 1);
    // 6. FF conv (fp16 mma) + residual -> d_out
    ff_conv_kernel<<<dim3(8, 16, 8), 256>>>(fb, fg, fbe, fm, fvv, (float*)d_out);
}